// round 1
// baseline (speedup 1.0000x reference)
#include <cuda_runtime.h>
#include <cstdint>
#include <math.h>

#define B_   128
#define C_   272
#define T_   1024
#define D_   270
#define KK_  1024
#define DPAD 320

// Scratch (device globals; allocation-free contract)
__device__ float g_cosP[KK_ * C_];            // 1.11 MB
__device__ float g_sinP[KK_ * C_];            // 1.11 MB
__device__ float g_Apart[8 * D_ * C_];        // 2.35 MB deterministic partials
__device__ float g_Wt[C_ * DPAD];             // softmax weights, transposed [c][d], zero-padded

// ---------------------------------------------------------------------------
// Stage 1: trig table. Replicate reference f32 arithmetic for the phase, then
// evaluate cos/sin of that exact f32 value in double (correctly rounded).
// ---------------------------------------------------------------------------
__global__ void trig_kernel(const float* __restrict__ loc) {
    int kl = blockIdx.x;          // k*32 + l
    int c  = threadIdx.x;         // 0..271
    float x = loc[2 * c];
    float y = loc[2 * c + 1];
    float kf = (float)(kl >> 5);
    float lf = (float)(kl & 31);
    float s = __fadd_rn(__fmul_rn(kf, x), __fmul_rn(lf, y));
    float p = __fmul_rn(6.28318530717958647692f, s);
    double sd, cd;
    sincos((double)p, &sd, &cd);
    g_cosP[kl * C_ + c] = (float)cd;
    g_sinP[kl * C_ + c] = (float)sd;
}

// ---------------------------------------------------------------------------
// Stage 2: A[d,c] partials. Grid (17 d-tiles, 8 kl-chunks), 272 threads (= c).
// Deterministic: each kl-chunk writes its own partial buffer.
// ---------------------------------------------------------------------------
__global__ void a_kernel(const float* __restrict__ zre, const float* __restrict__ zim) {
    __shared__ float s_zre[16][128];
    __shared__ float s_zim[16][128];
    int d0  = blockIdx.x * 16;
    int kl0 = blockIdx.y * 128;
    int tid = threadIdx.x;

    for (int i = tid; i < 16 * 128; i += 272) {
        int dd = i >> 7, j = i & 127;
        int d = d0 + dd;
        float vr = 0.f, vi = 0.f;
        if (d < D_) {
            vr = zre[d * KK_ + kl0 + j];
            vi = zim[d * KK_ + kl0 + j];
        }
        s_zre[dd][j] = vr;
        s_zim[dd][j] = vi;
    }
    __syncthreads();

    int c = tid;
    float acc[16];
#pragma unroll
    for (int i = 0; i < 16; i++) acc[i] = 0.f;

    for (int j = 0; j < 128; j++) {
        float cv = g_cosP[(kl0 + j) * C_ + c];
        float sv = g_sinP[(kl0 + j) * C_ + c];
#pragma unroll
        for (int i = 0; i < 16; i++)
            acc[i] = fmaf(s_zre[i][j], cv, fmaf(s_zim[i][j], sv, acc[i]));
    }

#pragma unroll
    for (int i = 0; i < 16; i++) {
        int d = d0 + i;
        if (d < D_)
            g_Apart[(blockIdx.y * D_ + d) * C_ + c] = acc[i];
    }
}

// ---------------------------------------------------------------------------
// Stage 3: softmax over c per row d; writes transposed+padded W.
// ---------------------------------------------------------------------------
__global__ void softmax_kernel() {
    int d   = blockIdx.x;
    int tid = threadIdx.x;   // 256 threads; c = tid and (256+tid for tid<16)
    __shared__ float s_red[256];

    float v0 = 0.f;
#pragma unroll
    for (int h = 0; h < 8; h++) v0 += g_Apart[(h * D_ + d) * C_ + tid];

    float v1 = __int_as_float(0xff800000);  // -inf
    if (tid < C_ - 256) {
        v1 = 0.f;
#pragma unroll
        for (int h = 0; h < 8; h++) v1 += g_Apart[(h * D_ + d) * C_ + 256 + tid];
    }

    s_red[tid] = fmaxf(v0, v1);
    __syncthreads();
    for (int s = 128; s > 0; s >>= 1) {
        if (tid < s) s_red[tid] = fmaxf(s_red[tid], s_red[tid + s]);
        __syncthreads();
    }
    float mx = s_red[0];
    __syncthreads();

    float e0 = expf(v0 - mx);
    float e1 = (tid < C_ - 256) ? expf(v1 - mx) : 0.f;
    s_red[tid] = e0 + e1;
    __syncthreads();
    for (int s = 128; s > 0; s >>= 1) {
        if (tid < s) s_red[tid] += s_red[tid + s];
        __syncthreads();
    }
    float inv = 1.f / s_red[0];

    g_Wt[tid * DPAD + d] = e0 * inv;
    if (tid < C_ - 256) g_Wt[(256 + tid) * DPAD + d] = e1 * inv;
}

// ---------------------------------------------------------------------------
// Stage 4: out[b,d,t] = sum_c w[d,c] * X[b,c,t]
// 64d x 128t tiles, 8-c chunks, packed fma.rn.f32x2 (2 fp32 FMA / instr).
// ---------------------------------------------------------------------------
#define FMA2(d_, a_, b_, c_) \
    asm("fma.rn.f32x2 %0, %1, %2, %3;" : "=l"(d_) : "l"(a_), "l"(b_), "l"(c_))

__global__ __launch_bounds__(256, 3) void bdt_kernel(const float* __restrict__ X,
                                                     float* __restrict__ out) {
    __shared__ __align__(16) float s_x[8][128];
    __shared__ unsigned long long s_wd[8][64];   // w duplicated into both f32x2 halves

    int t0  = blockIdx.x * 128;
    int d0  = blockIdx.y * 64;
    int b   = blockIdx.z;
    int tid = threadIdx.x;
    int tx  = tid & 15;       // t groups
    int ty  = tid >> 4;       // d groups

    unsigned long long acc[4][4];
#pragma unroll
    for (int i = 0; i < 4; i++)
#pragma unroll
        for (int p = 0; p < 4; p++) acc[i][p] = 0ULL;

    const float* Xb = X + (size_t)b * C_ * T_ + t0;
    int xc  = tid >> 5;          // 0..7
    int xt  = (tid & 31) * 4;    // 0..124
    int wc  = tid >> 4;          // (tid<128) 0..7
    int wd_ = (tid & 15) * 4;    // 0..60

    // prefetch chunk 0
    float4 xreg = *(const float4*)(Xb + (size_t)xc * T_ + xt);
    float4 wreg = make_float4(0.f, 0.f, 0.f, 0.f);
    if (tid < 128) wreg = *(const float4*)(g_Wt + wc * DPAD + d0 + wd_);

    for (int c0 = 0; c0 < C_; c0 += 8) {
        // stage current chunk into smem
        *(float4*)&s_x[xc][xt] = xreg;
        if (tid < 128) {
            unsigned long long u;
            unsigned r;
            r = __float_as_uint(wreg.x); asm("mov.b64 %0, {%1, %1};" : "=l"(u) : "r"(r)); s_wd[wc][wd_ + 0] = u;
            r = __float_as_uint(wreg.y); asm("mov.b64 %0, {%1, %1};" : "=l"(u) : "r"(r)); s_wd[wc][wd_ + 1] = u;
            r = __float_as_uint(wreg.z); asm("mov.b64 %0, {%1, %1};" : "=l"(u) : "r"(r)); s_wd[wc][wd_ + 2] = u;
            r = __float_as_uint(wreg.w); asm("mov.b64 %0, {%1, %1};" : "=l"(u) : "r"(r)); s_wd[wc][wd_ + 3] = u;
        }
        __syncthreads();

        // prefetch next chunk while computing current
        if (c0 + 8 < C_) {
            xreg = *(const float4*)(Xb + (size_t)(c0 + 8 + xc) * T_ + xt);
            if (tid < 128) wreg = *(const float4*)(g_Wt + (c0 + 8 + wc) * DPAD + d0 + wd_);
        }

#pragma unroll
        for (int cc = 0; cc < 8; cc++) {
            ulonglong2 xlo = *(ulonglong2*)&s_x[cc][tx * 4];
            ulonglong2 xhi = *(ulonglong2*)&s_x[cc][64 + tx * 4];
#pragma unroll
            for (int i = 0; i < 4; i++) {
                unsigned long long w = s_wd[cc][ty * 4 + i];
                FMA2(acc[i][0], xlo.x, w, acc[i][0]);
                FMA2(acc[i][1], xlo.y, w, acc[i][1]);
                FMA2(acc[i][2], xhi.x, w, acc[i][2]);
                FMA2(acc[i][3], xhi.y, w, acc[i][3]);
            }
        }
        __syncthreads();
    }

    int tb = t0 + tx * 4;
#pragma unroll
    for (int i = 0; i < 4; i++) {
        int d = d0 + ty * 4 + i;
        if (d < D_) {
            float* o = out + ((size_t)b * D_ + d) * T_;
            float2 a0 = *(float2*)&acc[i][0];
            float2 a1 = *(float2*)&acc[i][1];
            float2 a2 = *(float2*)&acc[i][2];
            float2 a3 = *(float2*)&acc[i][3];
            *(float4*)(o + tb)      = make_float4(a0.x, a0.y, a1.x, a1.y);
            *(float4*)(o + tb + 64) = make_float4(a2.x, a2.y, a3.x, a3.y);
        }
    }
}

// ---------------------------------------------------------------------------
extern "C" void kernel_launch(void* const* d_in, const int* in_sizes, int n_in,
                              void* d_out, int out_size) {
    const float* X   = (const float*)d_in[0];
    const float* loc = (const float*)d_in[1];
    const float* zre = (const float*)d_in[2];
    const float* zim = (const float*)d_in[3];
    float* out = (float*)d_out;

    trig_kernel<<<KK_, C_>>>(loc);
    a_kernel<<<dim3(17, 8), 272>>>(zre, zim);
    softmax_kernel<<<D_, 256>>>();
    bdt_kernel<<<dim3(T_ / 128, 5, B_), 256>>>(X, out);
}

// round 2
// speedup vs baseline: 1.0941x; 1.0941x over previous
#include <cuda_runtime.h>
#include <cstdint>
#include <math.h>

#define B_   128
#define C_   272
#define T_   1024
#define D_   270
#define KK_  1024
#define DPAD 320

// Scratch (device globals; allocation-free contract)
__device__ float g_cosP[KK_ * C_];            // 1.11 MB
__device__ float g_sinP[KK_ * C_];            // 1.11 MB
__device__ float g_Apart[8 * D_ * C_];        // 2.35 MB deterministic partials
__device__ float g_Wt[C_ * DPAD];             // softmax weights, transposed [c][d], zero-padded

// ---------------------------------------------------------------------------
// Stage 1: trig table. Replicate reference f32 arithmetic for the phase, then
// evaluate cos/sin of that exact f32 value in double (correctly rounded).
// ---------------------------------------------------------------------------
__global__ void trig_kernel(const float* __restrict__ loc) {
    int kl = blockIdx.x;          // k*32 + l
    int c  = threadIdx.x;         // 0..271
    float x = loc[2 * c];
    float y = loc[2 * c + 1];
    float kf = (float)(kl >> 5);
    float lf = (float)(kl & 31);
    float s = __fadd_rn(__fmul_rn(kf, x), __fmul_rn(lf, y));
    float p = __fmul_rn(6.28318530717958647692f, s);
    double sd, cd;
    sincos((double)p, &sd, &cd);
    g_cosP[kl * C_ + c] = (float)cd;
    g_sinP[kl * C_ + c] = (float)sd;
}

// ---------------------------------------------------------------------------
// Stage 2: A[d,c] partials. Grid (17 d-tiles, 8 kl-chunks), 272 threads (= c).
// Deterministic: each kl-chunk writes its own partial buffer.
// ---------------------------------------------------------------------------
__global__ void a_kernel(const float* __restrict__ zre, const float* __restrict__ zim) {
    __shared__ float s_zre[16][128];
    __shared__ float s_zim[16][128];
    int d0  = blockIdx.x * 16;
    int kl0 = blockIdx.y * 128;
    int tid = threadIdx.x;

    for (int i = tid; i < 16 * 128; i += 272) {
        int dd = i >> 7, j = i & 127;
        int d = d0 + dd;
        float vr = 0.f, vi = 0.f;
        if (d < D_) {
            vr = zre[d * KK_ + kl0 + j];
            vi = zim[d * KK_ + kl0 + j];
        }
        s_zre[dd][j] = vr;
        s_zim[dd][j] = vi;
    }
    __syncthreads();

    int c = tid;
    float acc[16];
#pragma unroll
    for (int i = 0; i < 16; i++) acc[i] = 0.f;

    for (int j = 0; j < 128; j++) {
        float cv = g_cosP[(kl0 + j) * C_ + c];
        float sv = g_sinP[(kl0 + j) * C_ + c];
#pragma unroll
        for (int i = 0; i < 16; i++)
            acc[i] = fmaf(s_zre[i][j], cv, fmaf(s_zim[i][j], sv, acc[i]));
    }

#pragma unroll
    for (int i = 0; i < 16; i++) {
        int d = d0 + i;
        if (d < D_)
            g_Apart[(blockIdx.y * D_ + d) * C_ + c] = acc[i];
    }
}

// ---------------------------------------------------------------------------
// Stage 3: softmax over c per row d; writes transposed+padded W.
// ---------------------------------------------------------------------------
__global__ void softmax_kernel() {
    int d   = blockIdx.x;
    int tid = threadIdx.x;   // 256 threads; c = tid and (256+tid for tid<16)
    __shared__ float s_red[256];

    float v0 = 0.f;
#pragma unroll
    for (int h = 0; h < 8; h++) v0 += g_Apart[(h * D_ + d) * C_ + tid];

    float v1 = __int_as_float(0xff800000);  // -inf
    if (tid < C_ - 256) {
        v1 = 0.f;
#pragma unroll
        for (int h = 0; h < 8; h++) v1 += g_Apart[(h * D_ + d) * C_ + 256 + tid];
    }

    s_red[tid] = fmaxf(v0, v1);
    __syncthreads();
    for (int s = 128; s > 0; s >>= 1) {
        if (tid < s) s_red[tid] = fmaxf(s_red[tid], s_red[tid + s]);
        __syncthreads();
    }
    float mx = s_red[0];
    __syncthreads();

    float e0 = expf(v0 - mx);
    float e1 = (tid < C_ - 256) ? expf(v1 - mx) : 0.f;
    s_red[tid] = e0 + e1;
    __syncthreads();
    for (int s = 128; s > 0; s >>= 1) {
        if (tid < s) s_red[tid] += s_red[tid + s];
        __syncthreads();
    }
    float inv = 1.f / s_red[0];

    g_Wt[tid * DPAD + d] = e0 * inv;
    if (tid < C_ - 256) g_Wt[(256 + tid) * DPAD + d] = e1 * inv;
}

// ---------------------------------------------------------------------------
// Stage 4: out[b,d,t] = sum_c w[d,c] * X[b,c,t]
// 256t x 64d tile per 256-thread CTA; 8d x 8t per thread; packed fma.rn.f32x2.
// w reads are warp-uniform broadcasts (warp <-> fixed ty) => ~1 crossbar cyc
// each; LDS demand ~12 cyc per warp-cc vs 16 cyc fma capacity -> fma-bound.
// ---------------------------------------------------------------------------
#define FMA2(d_, a_, b_, c_) \
    asm("fma.rn.f32x2 %0, %1, %2, %3;" : "=l"(d_) : "l"(a_), "l"(b_), "l"(c_))

__global__ __launch_bounds__(256, 2) void bdt_kernel(const float* __restrict__ X,
                                                     float* __restrict__ out) {
    __shared__ __align__(16) float s_x[8][256];                 // 8 KB
    __shared__ __align__(16) unsigned long long s_wd[8][64];    // 4 KB, w dup'd in halves

    int t0  = blockIdx.x * 256;
    int d0  = blockIdx.y * 64;
    int b   = blockIdx.z;
    int tid = threadIdx.x;
    int tx  = tid & 31;       // lane: t groups (warp-contiguous)
    int ty  = tid >> 5;       // warp id: d group (uniform per warp)

    unsigned long long acc[8][4];
#pragma unroll
    for (int j = 0; j < 8; j++)
#pragma unroll
        for (int p = 0; p < 4; p++) acc[j][p] = 0ULL;

    const float* Xb = X + (size_t)b * C_ * T_ + t0;
    int xc = tid >> 5;           // 0..7   (c row per warp)
    int xt = (tid & 31) * 8;     // 0..248 (32B per thread, coalesced)
    int wc = tid >> 4;           // 0..7   (first 128 threads)
    int wd = (tid & 15) * 4;

    // prefetch chunk 0
    float4 xr0 = *(const float4*)(Xb + (size_t)xc * T_ + xt);
    float4 xr1 = *(const float4*)(Xb + (size_t)xc * T_ + xt + 4);
    float4 wreg = make_float4(0.f, 0.f, 0.f, 0.f);
    if (tid < 128) wreg = *(const float4*)(g_Wt + wc * DPAD + d0 + wd);

    for (int c0 = 0; c0 < C_; c0 += 8) {
        // stage current chunk into smem
        *(float4*)&s_x[xc][xt]     = xr0;
        *(float4*)&s_x[xc][xt + 4] = xr1;
        if (tid < 128) {
            unsigned long long u;
            unsigned r;
            r = __float_as_uint(wreg.x); asm("mov.b64 %0, {%1, %1};" : "=l"(u) : "r"(r)); s_wd[wc][wd + 0] = u;
            r = __float_as_uint(wreg.y); asm("mov.b64 %0, {%1, %1};" : "=l"(u) : "r"(r)); s_wd[wc][wd + 1] = u;
            r = __float_as_uint(wreg.z); asm("mov.b64 %0, {%1, %1};" : "=l"(u) : "r"(r)); s_wd[wc][wd + 2] = u;
            r = __float_as_uint(wreg.w); asm("mov.b64 %0, {%1, %1};" : "=l"(u) : "r"(r)); s_wd[wc][wd + 3] = u;
        }
        __syncthreads();

        // prefetch next chunk while computing current
        if (c0 + 8 < C_) {
            xr0 = *(const float4*)(Xb + (size_t)(c0 + 8 + xc) * T_ + xt);
            xr1 = *(const float4*)(Xb + (size_t)(c0 + 8 + xc) * T_ + xt + 4);
            if (tid < 128) wreg = *(const float4*)(g_Wt + (c0 + 8 + wc) * DPAD + d0 + wd);
        }

#pragma unroll
        for (int cc = 0; cc < 8; cc++) {
            ulonglong2 xlo = *(ulonglong2*)&s_x[cc][tx * 4];          // t: tx*4..+3
            ulonglong2 xhi = *(ulonglong2*)&s_x[cc][128 + tx * 4];    // t: 128+tx*4..+3
            ulonglong2 w01 = *(ulonglong2*)&s_wd[cc][ty * 8 + 0];     // broadcast
            ulonglong2 w23 = *(ulonglong2*)&s_wd[cc][ty * 8 + 2];
            ulonglong2 w45 = *(ulonglong2*)&s_wd[cc][ty * 8 + 4];
            ulonglong2 w67 = *(ulonglong2*)&s_wd[cc][ty * 8 + 6];
            unsigned long long wv[8] = {w01.x, w01.y, w23.x, w23.y,
                                        w45.x, w45.y, w67.x, w67.y};
#pragma unroll
            for (int j = 0; j < 8; j++) {
                FMA2(acc[j][0], xlo.x, wv[j], acc[j][0]);
                FMA2(acc[j][1], xlo.y, wv[j], acc[j][1]);
                FMA2(acc[j][2], xhi.x, wv[j], acc[j][2]);
                FMA2(acc[j][3], xhi.y, wv[j], acc[j][3]);
            }
        }
        __syncthreads();
    }

    // write out: 8 d rows, 2x float4 per row
    int tb0 = t0 + tx * 4;
#pragma unroll
    for (int j = 0; j < 8; j++) {
        int d = d0 + ty * 8 + j;
        if (d < D_) {
            float* o = out + ((size_t)b * D_ + d) * T_;
            float2 a0 = *(float2*)&acc[j][0];
            float2 a1 = *(float2*)&acc[j][1];
            float2 a2 = *(float2*)&acc[j][2];
            float2 a3 = *(float2*)&acc[j][3];
            *(float4*)(o + tb0)       = make_float4(a0.x, a0.y, a1.x, a1.y);
            *(float4*)(o + tb0 + 128) = make_float4(a2.x, a2.y, a3.x, a3.y);
        }
    }
}

// ---------------------------------------------------------------------------
extern "C" void kernel_launch(void* const* d_in, const int* in_sizes, int n_in,
                              void* d_out, int out_size) {
    const float* X   = (const float*)d_in[0];
    const float* loc = (const float*)d_in[1];
    const float* zre = (const float*)d_in[2];
    const float* zim = (const float*)d_in[3];
    float* out = (float*)d_out;

    trig_kernel<<<KK_, C_>>>(loc);
    a_kernel<<<dim3(17, 8), 272>>>(zre, zim);
    softmax_kernel<<<D_, 256>>>();
    bdt_kernel<<<dim3(T_ / 256, 5, B_), 256>>>(X, out);
}

// round 4
// speedup vs baseline: 2.2541x; 2.0602x over previous
#include <cuda_runtime.h>
#include <cuda_bf16.h>
#include <cstdint>
#include <math.h>

#define B_   128
#define C_   272
#define T_   1024
#define D_   270
#define KK_  1024
#define DP   288      // padded d rows for W (3 x 96)
#define CP   320      // padded c cols for W

// Scratch (device globals; allocation-free contract). Zero-initialized.
__device__ float g_cosP[KK_ * C_];
__device__ float g_sinP[KK_ * C_];
__device__ float g_Apart[8 * D_ * C_];
__device__ __nv_bfloat16 g_Wh[DP * CP];   // softmax weights hi, [d][c], zero-padded
__device__ __nv_bfloat16 g_Wl[DP * CP];   // softmax weights lo

__device__ __forceinline__ uint32_t smem_u32(const void* p) {
    uint32_t a;
    asm("{ .reg .u64 t; cvta.to.shared.u64 t, %1; cvt.u32.u64 %0, t; }" : "=r"(a) : "l"(p));
    return a;
}

#define LDSM_X4(r, a)                                                        \
    asm volatile("ldmatrix.sync.aligned.m8n8.x4.shared.b16 {%0,%1,%2,%3}, [%4];" \
        : "=r"((r)[0]), "=r"((r)[1]), "=r"((r)[2]), "=r"((r)[3]) : "r"(a))
#define LDSM_X4_T(r, a)                                                      \
    asm volatile("ldmatrix.sync.aligned.m8n8.x4.trans.shared.b16 {%0,%1,%2,%3}, [%4];" \
        : "=r"((r)[0]), "=r"((r)[1]), "=r"((r)[2]), "=r"((r)[3]) : "r"(a))

#define MMA16816(d, a, b0v, b1v)                                             \
    asm volatile("mma.sync.aligned.m16n8k16.row.col.f32.bf16.bf16.f32 "      \
        "{%0,%1,%2,%3}, {%4,%5,%6,%7}, {%8,%9}, {%0,%1,%2,%3};"              \
        : "+f"((d)[0]), "+f"((d)[1]), "+f"((d)[2]), "+f"((d)[3])             \
        : "r"((a)[0]), "r"((a)[1]), "r"((a)[2]), "r"((a)[3]),                \
          "r"(b0v), "r"(b1v))

// ---------------------------------------------------------------------------
// Stage 1: trig table (reference-exact f32 phase, correctly-rounded cos/sin).
// ---------------------------------------------------------------------------
__global__ void trig_kernel(const float* __restrict__ loc) {
    int kl = blockIdx.x;
    int c  = threadIdx.x;
    float x = loc[2 * c];
    float y = loc[2 * c + 1];
    float kf = (float)(kl >> 5);
    float lf = (float)(kl & 31);
    float s = __fadd_rn(__fmul_rn(kf, x), __fmul_rn(lf, y));
    float p = __fmul_rn(6.28318530717958647692f, s);
    double sd, cd;
    sincos((double)p, &sd, &cd);
    g_cosP[kl * C_ + c] = (float)cd;
    g_sinP[kl * C_ + c] = (float)sd;
}

// ---------------------------------------------------------------------------
// Stage 2: A[d,c] partials (deterministic, per-kl-chunk buffers).
// ---------------------------------------------------------------------------
__global__ void a_kernel(const float* __restrict__ zre, const float* __restrict__ zim) {
    __shared__ float s_zre[16][128];
    __shared__ float s_zim[16][128];
    int d0  = blockIdx.x * 16;
    int kl0 = blockIdx.y * 128;
    int tid = threadIdx.x;

    for (int i = tid; i < 16 * 128; i += 272) {
        int dd = i >> 7, j = i & 127;
        int d = d0 + dd;
        float vr = 0.f, vi = 0.f;
        if (d < D_) {
            vr = zre[d * KK_ + kl0 + j];
            vi = zim[d * KK_ + kl0 + j];
        }
        s_zre[dd][j] = vr;
        s_zim[dd][j] = vi;
    }
    __syncthreads();

    int c = tid;
    float acc[16];
#pragma unroll
    for (int i = 0; i < 16; i++) acc[i] = 0.f;

    for (int j = 0; j < 128; j++) {
        float cv = g_cosP[(kl0 + j) * C_ + c];
        float sv = g_sinP[(kl0 + j) * C_ + c];
#pragma unroll
        for (int i = 0; i < 16; i++)
            acc[i] = fmaf(s_zre[i][j], cv, fmaf(s_zim[i][j], sv, acc[i]));
    }

#pragma unroll
    for (int i = 0; i < 16; i++) {
        int d = d0 + i;
        if (d < D_)
            g_Apart[(blockIdx.y * D_ + d) * C_ + c] = acc[i];
    }
}

// ---------------------------------------------------------------------------
// Stage 3: softmax over c per row d; emit bf16 hi/lo split weights [d][c].
// ---------------------------------------------------------------------------
__global__ void softmax_kernel() {
    int d   = blockIdx.x;
    int tid = threadIdx.x;   // 256
    __shared__ float s_red[256];

    float v0 = 0.f;
#pragma unroll
    for (int h = 0; h < 8; h++) v0 += g_Apart[(h * D_ + d) * C_ + tid];

    float v1 = __int_as_float(0xff800000);
    if (tid < C_ - 256) {
        v1 = 0.f;
#pragma unroll
        for (int h = 0; h < 8; h++) v1 += g_Apart[(h * D_ + d) * C_ + 256 + tid];
    }

    s_red[tid] = fmaxf(v0, v1);
    __syncthreads();
    for (int s = 128; s > 0; s >>= 1) {
        if (tid < s) s_red[tid] = fmaxf(s_red[tid], s_red[tid + s]);
        __syncthreads();
    }
    float mx = s_red[0];
    __syncthreads();

    float e0 = expf(v0 - mx);
    float e1 = (tid < C_ - 256) ? expf(v1 - mx) : 0.f;
    s_red[tid] = e0 + e1;
    __syncthreads();
    for (int s = 128; s > 0; s >>= 1) {
        if (tid < s) s_red[tid] += s_red[tid + s];
        __syncthreads();
    }
    float inv = 1.f / s_red[0];

    float w0 = e0 * inv;
    __nv_bfloat16 h0 = __float2bfloat16(w0);
    g_Wh[d * CP + tid] = h0;
    g_Wl[d * CP + tid] = __float2bfloat16(w0 - __bfloat162float(h0));
    if (tid < C_ - 256) {
        float w1 = e1 * inv;
        __nv_bfloat16 h1 = __float2bfloat16(w1);
        g_Wh[d * CP + 256 + tid] = h1;
        g_Wl[d * CP + 256 + tid] = __float2bfloat16(w1 - __bfloat162float(h1));
    }
}

// ---------------------------------------------------------------------------
// Stage 4: out[b,d,t] = sum_c w[d,c] * X[b,c,t] via mma.sync bf16, 3 passes.
// CTA: 96d x 128t, K chunks of 32 c (9 chunks). Warps 2(d) x 4(t),
// warp tile 48d x 32t -> 3 m-tiles x 4 n-tiles of m16n8k16.
// ---------------------------------------------------------------------------
#define ASTRIDE 80
#define BSTRIDE 272

__device__ __forceinline__ void bf16split2(float f0, float f1, uint32_t& hi, uint32_t& lo) {
    __nv_bfloat16 h0 = __float2bfloat16(f0);
    __nv_bfloat16 h1 = __float2bfloat16(f1);
    __nv_bfloat16 l0 = __float2bfloat16(f0 - __bfloat162float(h0));
    __nv_bfloat16 l1 = __float2bfloat16(f1 - __bfloat162float(h1));
    hi = (uint32_t)__bfloat16_as_ushort(h0) | ((uint32_t)__bfloat16_as_ushort(h1) << 16);
    lo = (uint32_t)__bfloat16_as_ushort(l0) | ((uint32_t)__bfloat16_as_ushort(l1) << 16);
}

__global__ __launch_bounds__(256, 2) void bdt_mma_kernel(const float* __restrict__ X,
                                                         float* __restrict__ out) {
    __shared__ __align__(16) uint8_t sAh[96 * ASTRIDE];
    __shared__ __align__(16) uint8_t sAl[96 * ASTRIDE];
    __shared__ __align__(16) uint8_t sBh[32 * BSTRIDE];
    __shared__ __align__(16) uint8_t sBl[32 * BSTRIDE];

    int tid  = threadIdx.x;
    int wid  = tid >> 5;
    int lane = tid & 31;
    int d0   = blockIdx.x * 96;
    int t0   = blockIdx.y * 128;
    int b    = blockIdx.z;
    int wd   = wid >> 2;       // 0..1
    int wt   = wid & 3;        // 0..3

    float acc[3][4][4];
#pragma unroll
    for (int m = 0; m < 3; m++)
#pragma unroll
        for (int n = 0; n < 4; n++)
#pragma unroll
            for (int k = 0; k < 4; k++) acc[m][n][k] = 0.f;

    uint32_t aAh = smem_u32(sAh), aAl = smem_u32(sAl);
    uint32_t aBh = smem_u32(sBh), aBl = smem_u32(sBl);

    // ldmatrix lane address offsets (same pattern for A and B)
    uint32_t laA = (uint32_t)((lane & 15) * ASTRIDE + (lane >> 4) * 16);
    uint32_t laB = (uint32_t)((lane & 15) * BSTRIDE + (lane >> 4) * 16);

    // X prefetch: thread -> (c = pc, t = pt..pt+15)
    int pc = tid >> 3;             // 0..31
    int pt = (tid & 7) * 16;       // 0..112
    const float* Xbase = X + (size_t)b * C_ * T_ + t0 + pt;

    float4 xv[4];
#pragma unroll
    for (int j = 0; j < 4; j++)
        xv[j] = *(const float4*)(Xbase + (size_t)pc * T_ + j * 4);

    for (int ch = 0; ch < 9; ch++) {
        int c0 = ch * 32;
        int nc = (ch == 8) ? 16 : 32;

        if (ch > 0) __syncthreads();   // prev chunk's mma done reading smem

        // ---- B staging: X chunk -> bf16 hi/lo [c][t] ----
        if (pc < nc) {
            uint32_t hi[8], lo[8];
#pragma unroll
            for (int j = 0; j < 4; j++) {
                bf16split2(xv[j].x, xv[j].y, hi[2 * j], lo[2 * j]);
                bf16split2(xv[j].z, xv[j].w, hi[2 * j + 1], lo[2 * j + 1]);
            }
            uint32_t off = (uint32_t)(pc * BSTRIDE + pt * 2);
            *(uint4*)(sBh + off)      = make_uint4(hi[0], hi[1], hi[2], hi[3]);
            *(uint4*)(sBh + off + 16) = make_uint4(hi[4], hi[5], hi[6], hi[7]);
            *(uint4*)(sBl + off)      = make_uint4(lo[0], lo[1], lo[2], lo[3]);
            *(uint4*)(sBl + off + 16) = make_uint4(lo[4], lo[5], lo[6], lo[7]);
        }

        // ---- A staging: W chunk (L2-hot) ----
        for (int i = tid; i < 96 * 4; i += 256) {
            int row = i >> 2, seg = i & 3;
            if (seg * 8 < nc) {
                int src = (d0 + row) * CP + c0 + seg * 8;
                uint4 vh = *(const uint4*)&g_Wh[src];
                uint4 vl = *(const uint4*)&g_Wl[src];
                uint32_t off = (uint32_t)(row * ASTRIDE + seg * 16);
                *(uint4*)(sAh + off) = vh;
                *(uint4*)(sAl + off) = vl;
            }
        }
        __syncthreads();

        // ---- prefetch next chunk into regs ----
        if (ch < 8) {
            int ncn = (ch == 7) ? 16 : 32;
            if (pc < ncn) {
#pragma unroll
                for (int j = 0; j < 4; j++)
                    xv[j] = *(const float4*)(Xbase + (size_t)((ch + 1) * 32 + pc) * T_ + j * 4);
            }
        }

        // ---- mma ----
        int nks = nc >> 4;   // 2 or 1
        uint32_t Abase_h = aAh + (uint32_t)(wd * 48 * ASTRIDE) + laA;
        uint32_t Abase_l = aAl + (uint32_t)(wd * 48 * ASTRIDE) + laA;
        uint32_t Bbase_h = aBh + (uint32_t)(wt * 64) + laB;
        uint32_t Bbase_l = aBl + (uint32_t)(wt * 64) + laB;

        for (int ks = 0; ks < nks; ks++) {
            uint32_t ao = (uint32_t)(ks * 32);
            uint32_t bo = (uint32_t)(ks * 16 * BSTRIDE);

            uint32_t ah[3][4], al[3][4];
#pragma unroll
            for (int mt = 0; mt < 3; mt++) {
                LDSM_X4(ah[mt], Abase_h + (uint32_t)(mt * 16 * ASTRIDE) + ao);
                LDSM_X4(al[mt], Abase_l + (uint32_t)(mt * 16 * ASTRIDE) + ao);
            }
            uint32_t bh[8], bl[8];    // [nt*2 + half]
            LDSM_X4_T(bh,     Bbase_h + bo);        // n-tiles 0,1
            LDSM_X4_T(bh + 4, Bbase_h + bo + 32);   // n-tiles 2,3
            LDSM_X4_T(bl,     Bbase_l + bo);
            LDSM_X4_T(bl + 4, Bbase_l + bo + 32);

#pragma unroll
            for (int mt = 0; mt < 3; mt++) {
#pragma unroll
                for (int nt = 0; nt < 4; nt++) {
                    MMA16816(acc[mt][nt], ah[mt], bh[2 * nt], bh[2 * nt + 1]);
                    MMA16816(acc[mt][nt], ah[mt], bl[2 * nt], bl[2 * nt + 1]);
                    MMA16816(acc[mt][nt], al[mt], bh[2 * nt], bh[2 * nt + 1]);
                }
            }
        }
    }

    // ---- epilogue: fragment rows = d, cols = t ----
#pragma unroll
    for (int mt = 0; mt < 3; mt++) {
        int dr = d0 + wd * 48 + mt * 16 + (lane >> 2);
#pragma unroll
        for (int nt = 0; nt < 4; nt++) {
            int tt = t0 + wt * 32 + nt * 8 + (lane & 3) * 2;
            if (dr < D_)
                *(float2*)(out + ((size_t)b * D_ + dr) * T_ + tt) =
                    make_float2(acc[mt][nt][0], acc[mt][nt][1]);
            if (dr + 8 < D_)
                *(float2*)(out + ((size_t)b * D_ + dr + 8) * T_ + tt) =
                    make_float2(acc[mt][nt][2], acc[mt][nt][3]);
        }
    }
}

// ---------------------------------------------------------------------------
extern "C" void kernel_launch(void* const* d_in, const int* in_sizes, int n_in,
                              void* d_out, int out_size) {
    const float* X   = (const float*)d_in[0];
    const float* loc = (const float*)d_in[1];
    const float* zre = (const float*)d_in[2];
    const float* zim = (const float*)d_in[3];
    float* out = (float*)d_out;

    trig_kernel<<<KK_, C_>>>(loc);
    a_kernel<<<dim3(17, 8), 272>>>(zre, zim);
    softmax_kernel<<<D_, 256>>>();
    bdt_mma_kernel<<<dim3(3, 8, B_), 256>>>(X, out);
}